// round 16
// baseline (speedup 1.0000x reference)
#include <cuda_runtime.h>
#include <cuda_bf16.h>
#include <cstdint>

#define HWF   50176
#define IMG_B 12845056

// ---------------- device scratch (split bf16 hi/lo) ----------------
__device__ unsigned short g_KLh[16056320], g_KLl[16056320];   // Kp = Mqk·skip: [b][pix(15680)][256]
__device__ unsigned short g_VLh[16056320], g_VLl[16056320];   // V = Wv·skip+bv: [b][pix][256]
__device__ unsigned short g_Wh[131072], g_Wl[131072];         // split [2][256][256]: Mqk, Wv
__device__ float g_Mqk[65536];                                 // WqT·Wk fp32
__device__ float g_u[256];                                     // WkT·bq
__device__ float g_t[62720];                                   // u·skip per [b][pix]

// ---------------- helpers ----------------
__device__ __forceinline__ void split_f32(float v, unsigned short& h, unsigned short& l) {
  __nv_bfloat16 bh = __float2bfloat16(v);
  h = __bfloat16_as_ushort(bh);
  l = __bfloat16_as_ushort(__float2bfloat16(v - __bfloat162float(bh)));
}
__device__ __forceinline__ void split2(float a, float b, unsigned& uh, unsigned& ul) {
  unsigned short h0, l0, h1, l1; split_f32(a, h0, l0); split_f32(b, h1, l1);
  uh = (unsigned)h0 | ((unsigned)h1 << 16);
  ul = (unsigned)l0 | ((unsigned)l1 << 16);
}
__device__ __forceinline__ void mma_bf16(float d[4], const unsigned a[4], const unsigned b[2]) {
  asm volatile("mma.sync.aligned.m16n8k16.row.col.f32.bf16.bf16.f32 "
               "{%0,%1,%2,%3}, {%4,%5,%6,%7}, {%8,%9}, {%0,%1,%2,%3};\n"
               : "+f"(d[0]), "+f"(d[1]), "+f"(d[2]), "+f"(d[3])
               : "r"(a[0]), "r"(a[1]), "r"(a[2]), "r"(a[3]), "r"(b[0]), "r"(b[1]));
}
#define LDSM4(r, addr) \
  asm volatile("ldmatrix.sync.aligned.m8n8.x4.shared.b16 {%0,%1,%2,%3},[%4];" \
               : "=r"(r[0]), "=r"(r[1]), "=r"(r[2]), "=r"(r[3]) : "r"(addr))
#define LDSM4T(r, addr) \
  asm volatile("ldmatrix.sync.aligned.m8n8.x4.trans.shared.b16 {%0,%1,%2,%3},[%4];" \
               : "=r"(r[0]), "=r"(r[1]), "=r"(r[2]), "=r"(r[3]) : "r"(addr))
#define CP16(sm, gp, sz) \
  asm volatile("cp.async.cg.shared.global [%0],[%1],16,%2;\n" :: "r"(sm), "l"(gp), "r"(sz))
#define CPCOMMIT() asm volatile("cp.async.commit_group;\n" ::: "memory")
#define CPWAIT1()  asm volatile("cp.async.wait_group 1;\n" ::: "memory")
#define CPWAIT0()  asm volatile("cp.async.wait_group 0;\n" ::: "memory")

// window pixel for patch n, window slot j (0..127). -1 = zero pad.
__device__ __forceinline__ int win_pix(int n, int j) {
  const int ah = (n >> 4) & 15, aw = n & 15;
  if (j < 81) {
    const int jr = j / 9, jc = j - jr * 9;
    const int gr = min(max(7 * ah - 1 + jr, 0), 111);
    const int gc = min(max(7 * aw - 1 + jc, 0), 111);
    return gr * 112 + gc;
  }
  if (j >= 88 && j < 113) {
    const int jj = j - 88;
    const int jr = jj / 5, jc = jj - jr * 5;
    const int gr = min(max(((7 * ah - 1) >> 1) + jr, 0), 55);
    const int gc = min(max(((7 * aw - 1) >> 1) + jc, 0), 55);
    return 12544 + gr * 56 + gc;
  }
  return -1;
}

// ---------------- Mqk = Wq^T Wk (fp32 tiled) ----------------
__global__ void __launch_bounds__(256) mqk_kernel(
    const float* __restrict__ Wq, const float* __restrict__ Wk)
{
  __shared__ float A[16][17], B[16][17];
  const int tx = threadIdx.x & 15, ty = threadIdx.x >> 4;
  const int c0 = blockIdx.x * 16, cp0 = blockIdx.y * 16;
  float acc = 0.f;
  for (int o0 = 0; o0 < 256; o0 += 16) {
    A[ty][tx] = Wq[(o0 + ty) * 256 + c0 + tx];
    B[ty][tx] = Wk[(o0 + ty) * 256 + cp0 + tx];
    __syncthreads();
#pragma unroll
    for (int o = 0; o < 16; o++) acc += A[o][ty] * B[o][tx];
    __syncthreads();
  }
  g_Mqk[(c0 + ty) * 256 + cp0 + tx] = acc;
}

// ---------------- u = Wk^T bq ----------------
__global__ void u_kernel(const float* __restrict__ Wk, const float* __restrict__ bq)
{
  const int k = threadIdx.x;
  float s = 0.f;
  for (int o = 0; o < 256; o++) s += bq[o] * Wk[o * 256 + k];
  g_u[k] = s;
}

// ---------------- t[b][pix] = u · skip ----------------
__global__ void __launch_bounds__(256) t_kernel(
    const float* __restrict__ skip0, const float* __restrict__ skip1)
{
  __shared__ float us[256];
  us[threadIdx.x] = g_u[threadIdx.x];
  __syncthreads();
  const int idx = blockIdx.x * 256 + threadIdx.x;   // < 62720 exactly (245 blocks)
  const int b = idx / 15680, pix = idx - b * 15680;
  const float* src; int hw, hwin;
  if (pix < 12544) { src = skip0; hw = pix; hwin = 12544; }
  else             { src = skip1; hw = pix - 12544; hwin = 3136; }
  const float* p = src + (size_t)b * 256 * hwin + hw;
  float s = 0.f;
  for (int k = 0; k < 256; k++) s += us[k] * p[(size_t)k * hwin];
  g_t[idx] = s;
}

// ---------------- split {Mqk, Wv} -> g_Wh/g_Wl ----------------
__global__ void __launch_bounds__(256) splitW_kernel(const float* __restrict__ Wv)
{
  const int t = blockIdx.x * 256 + threadIdx.x;   // 32768 threads x 4 elems
  const int wi = t / 16384, i = t - wi * 16384;
  const float4 v = ((const float4*)(wi == 0 ? g_Mqk : Wv))[i];
  unsigned uh0, ul0, uh1, ul1;
  split2(v.x, v.y, uh0, ul0);
  split2(v.z, v.w, uh1, ul1);
  *(uint2*)&g_Wh[t * 4] = make_uint2(uh0, uh1);
  *(uint2*)&g_Wl[t * 4] = make_uint2(ul0, ul1);
}

// ==================================================================
// Projection kernel (low-res only): Kp = Mqk·skip ; V = Wv·skip + bv
// ==================================================================
__global__ void __launch_bounds__(224, 2) proj_kernel(
    const float* __restrict__ skip0, const float* __restrict__ skip1,
    const float* __restrict__ bv)
{
  constexpr int NF = 16;
  extern __shared__ __align__(16) unsigned char smem[];
  unsigned short* Ah = (unsigned short*)smem;            // [112][40]
  unsigned short* Al = (unsigned short*)(smem + 8960);

  const int tid = threadIdx.x, warp = tid >> 5, lane = tid & 31;
  const int qr = lane >> 2, kc2 = (lane & 3) * 2;
  const int t8 = lane >> 3, l7 = lane & 7;

  // segment decode: [0,448) Kp-s0, [448,560) Kp-s1, [560,1008) V-s0, [1008,1120) V-s1
  int t = blockIdx.x;
  const float* src;
  int hwin, offs, dst, wsel;
  if (t < 448)       {            src = skip0; hwin = 12544; offs = 0;     dst = 1; wsel = 0; }
  else if (t < 560)  { t -= 448;  src = skip1; hwin = 3136;  offs = 12544; dst = 1; wsel = 0; }
  else if (t < 1008) { t -= 560;  src = skip0; hwin = 12544; offs = 0;     dst = 2; wsel = 1; }
  else               { t -= 1008; src = skip1; hwin = 3136;  offs = 12544; dst = 2; wsel = 1; }
  const int p0 = t * 112;
  const int b = p0 / hwin;
  const int o0 = blockIdx.y * 128;
  const float* xb = src + (size_t)b * 256 * hwin + (p0 - b * hwin);
  const unsigned wbase = (unsigned)wsel * 65536 + (unsigned)o0 * 256;

  const int ap = tid % 112, akb = tid / 112;

  const unsigned sbase  = (unsigned)__cvta_generic_to_shared(smem);
  const unsigned a_addr = sbase + ((warp * 16 + l7 + (t8 & 1) * 8) * 40 + (t8 >> 1) * 8) * 2;
  const unsigned b_base = sbase + 17920 + ((l7 + (t8 >> 1) * 8) * 40 + (t8 & 1) * 8) * 2;

  float acc[NF][4];
#pragma unroll
  for (int i = 0; i < NF; i++) { acc[i][0] = acc[i][1] = acc[i][2] = acc[i][3] = 0.f; }

  auto stageB = [&](int ch, int buf) {
    const unsigned sb = sbase + 17920 + (unsigned)buf * 20480;
    const int k0 = ch * 32;
    for (int idx = tid; idx < 128 * 4; idx += 224) {
      const int r = idx >> 2, q = (idx & 3) * 8;
      const unsigned g = wbase + r * 256 + k0 + q;
      CP16(sb + r * 80 + q * 2, g_Wh + g, 16);
      CP16(sb + 10240 + r * 80 + q * 2, g_Wl + g, 16);
    }
    CPCOMMIT();
  };

  float ar[16];
#pragma unroll
  for (int i = 0; i < 16; i++)
    ar[i] = xb[(size_t)(akb + 2 * i) * hwin + ap];
  stageB(0, 0);

#pragma unroll 1
  for (int ch = 0; ch < 8; ch++) {
    const int buf = ch & 1;
#pragma unroll
    for (int i = 0; i < 16; i++) {
      unsigned short h, l; split_f32(ar[i], h, l);
      Ah[ap * 40 + akb + 2 * i] = h;
      Al[ap * 40 + akb + 2 * i] = l;
    }
    if (ch < 7) { stageB(ch + 1, buf ^ 1); CPWAIT1(); }
    else        { CPWAIT0(); }
    __syncthreads();
    if (ch < 7) {
      const int nk0 = ch * 32 + 32;
#pragma unroll
      for (int i = 0; i < 16; i++)
        ar[i] = xb[(size_t)(nk0 + akb + 2 * i) * hwin + ap];
    }
    const unsigned bo = b_base + (unsigned)buf * 20480;
#pragma unroll
    for (int kk = 0; kk < 2; kk++) {
      unsigned ahf[4], alf[4];
      LDSM4(ahf, a_addr + kk * 32);
      LDSM4(alf, a_addr + 8960 + kk * 32);
#pragma unroll
      for (int nf = 0; nf < NF; nf += 2) {
        unsigned bh[4], bl4[4];
        LDSM4(bh,  bo + nf * 640 + kk * 32);
        LDSM4(bl4, bo + 10240 + nf * 640 + kk * 32);
        mma_bf16(acc[nf], ahf, bh);      mma_bf16(acc[nf + 1], ahf, bh + 2);
        mma_bf16(acc[nf], alf, bh);      mma_bf16(acc[nf + 1], alf, bh + 2);
        mma_bf16(acc[nf], ahf, bl4);     mma_bf16(acc[nf + 1], ahf, bl4 + 2);
      }
    }
    __syncthreads();
  }

  unsigned short* dh = (dst == 2) ? g_VLh : g_KLh;
  unsigned short* dl = (dst == 2) ? g_VLl : g_KLl;
#pragma unroll
  for (int half = 0; half < 2; half++) {
    const int p = p0 + warp * 16 + qr + half * 8;
    const int pl = p - b * hwin;
    const size_t dsto = ((size_t)b * 15680 + offs + pl) * 256;
#pragma unroll
    for (int nf = 0; nf < NF; nf++) {
      const int o = o0 + nf * 8 + kc2;
      const float b0 = (dst == 2) ? bv[o] : 0.f;
      const float b1 = (dst == 2) ? bv[o + 1] : 0.f;
      unsigned uh, ul;
      split2(acc[nf][half * 2] + b0, acc[nf][half * 2 + 1] + b1, uh, ul);
      *(unsigned*)&dh[dsto + o] = uh;
      *(unsigned*)&dl[dsto + o] = ul;
    }
  }
}

// ---------------- softmax expansion helpers ----------------
template<int WS>
__device__ __forceinline__ float pass_max(
    const float* SLr, const int* JRp, const float* FRp, const float* FCs,
    const int* cs, int mi0)
{
  float mx = -1e30f;
#pragma unroll 1
  for (int mi = mi0; mi < mi0 + 7; mi++) {
    const int jr = JRp[mi]; const float fr = FRp[mi];
    float H[WS];
#pragma unroll
    for (int jc = 0; jc < WS; jc++)
      H[jc] = (1.f - fr) * SLr[jr * WS + jc] + fr * SLr[(jr + 1) * WS + jc];
#pragma unroll
    for (int jc = 0; jc + 1 < WS; jc++) {
      for (int mj = cs[jc]; mj < cs[jc + 1]; mj++) {
        const float fc = FCs[mj];
        mx = fmaxf(mx, (1.f - fc) * H[jc] + fc * H[jc + 1]);
      }
    }
  }
  return mx;
}
template<int WS>
__device__ __forceinline__ float pass_fold(
    const float* SLr, float* PLr, const int* JRp, const float* FRp, const float* FCs,
    const int* cs, int mi0, float mx)
{
  float sum = 0.f;
#pragma unroll 1
  for (int mi = mi0; mi < mi0 + 7; mi++) {
    const int jr = JRp[mi]; const float fr = FRp[mi];
    float H[WS], T[WS];
#pragma unroll
    for (int jc = 0; jc < WS; jc++) {
      H[jc] = (1.f - fr) * SLr[jr * WS + jc] + fr * SLr[(jr + 1) * WS + jc];
      T[jc] = 0.f;
    }
#pragma unroll
    for (int jc = 0; jc + 1 < WS; jc++) {
      for (int mj = cs[jc]; mj < cs[jc + 1]; mj++) {
        const float fc = FCs[mj];
        const float e = __expf((1.f - fc) * H[jc] + fc * H[jc + 1] - mx);
        sum += e;
        T[jc]     += e * (1.f - fc);
        T[jc + 1] += e * fc;
      }
    }
#pragma unroll
    for (int jc = 0; jc < WS; jc++) {
      atomicAdd(&PLr[jr * WS + jc],       (1.f - fr) * T[jc]);
      atomicAdd(&PLr[(jr + 1) * WS + jc], fr * T[jc]);
    }
  }
  return sum;
}

// ==================================================================
// Fused attention kernel: S_low = x·Kp (+t) with x read DIRECTLY from
// input (register-prefetched transpose+split in staging; no X array)
//   -> softmax expand/fold -> P smem -> AV GEMM (V via window table,
//   ldmatrix.trans) -> unpatchified out.
// ==================================================================
__global__ void __launch_bounds__(224, 1) attn_kernel(
    const float* __restrict__ x, float* __restrict__ outp)
{
  // smem map (bytes):
  //  [0,17920)        A (x split): Ah[112][40], Al +8960   (single buffer)
  //  [17920,56320)    K double buffers (2 x 19200: hi[120][40], lo +9600)
  //  fold overlay:    SL[112][124] f32 @0, PL[112][128] f32 @55552 (..112896)
  //  [112896,114416)  LUTs: JR FR JC FC tbl(128) CS ts
  //  [114432,175360)  P split: Ph[112][136], Pl +30464
  //  [175360,210176)  V double buffers (2 x 17408: hi[32][136], lo +8704)
  extern __shared__ __align__(16) unsigned char smem[];
  const unsigned sbase = (unsigned)__cvta_generic_to_shared(smem);
  constexpr unsigned OFF_PH = 114432, OFF_VB = 175360, VBUF = 17408;
  constexpr unsigned OFF_K = 17920, KBUF = 19200, KHB = 9600;
  int*   JR  = (int*)(smem + 112896);
  float* FR  = (float*)(smem + 113008);
  int*   JC  = (int*)(smem + 113120);
  float* FC  = (float*)(smem + 113232);
  int*   tbl = (int*)(smem + 113344);   // 128 ints
  int*   CS  = (int*)(smem + 113856);   // 20 ints
  float* ts  = (float*)(smem + 113936); // 120 floats

  const int tid = threadIdx.x, warp = tid >> 5, lane = tid & 31;
  const int qr = lane >> 2, kc2 = (lane & 3) * 2;
  const int t8 = lane >> 3, l7 = lane & 7;
  const int n = blockIdx.z, b = n >> 8;
  const int Lb = blockIdx.x * 112;
  const int ah = (n >> 4) & 15, aw = n & 15;

  for (int j = tid; j < 128; j += 224) tbl[j] = win_pix(n, j);
  if (tid < 28) {
    const int s = tid / 14, u = tid - s * 14;
    const float sc = s ? 0.25f : 0.5f;
    const int baseh = s ? ((7 * ah - 1) >> 1) : (7 * ah - 1);
    const int basew = s ? ((7 * aw - 1) >> 1) : (7 * aw - 1);
    float sh = (14 * ah + u + 0.5f) * sc - 0.5f;
    int ih = (int)floorf(sh);
    JR[tid] = ih - baseh; FR[tid] = sh - (float)ih;
    sh = (14 * aw + u + 0.5f) * sc - 0.5f;
    ih = (int)floorf(sh);
    JC[tid] = ih - basew; FC[tid] = sh - (float)ih;
  }
  __syncthreads();
  if (tid < 2) {
    const int WS = tid ? 5 : 9;
    int* cs = CS + tid * 10;
    for (int k = 0; k < WS; k++) {
      int cnt = 0;
      for (int u = 0; u < 14; u++) if (JC[tid * 14 + u] < k) cnt++;
      cs[k] = cnt;
    }
  }
  for (int j = tid; j < 120; j += 224)
    ts[j] = (tbl[j] >= 0) ? g_t[b * 15680 + tbl[j]] : 0.f;

  unsigned short* Ah = (unsigned short*)smem;
  unsigned short* Al = (unsigned short*)(smem + 8960);
  const unsigned a_addr = sbase + ((warp * 16 + l7 + (t8 & 1) * 8) * 40 + (t8 >> 1) * 8) * 2;
  const unsigned b_addr = sbase + OFF_K + ((l7 + (t8 >> 1) * 8) * 40 + (t8 & 1) * 8) * 2;

  // per-thread x source (direct from input, transposed access; 14-contig runs)
  const int ap = tid % 112, akb = tid / 112;
  const int lpix = Lb + ap;
  const int lcl = min(lpix, 195);
  const int hh = ah * 14 + lcl / 14, ww = aw * 14 + lcl % 14;
  const float* xb = x + (size_t)b * IMG_B + hh * 224 + ww;
  const bool xvalid = (lpix < 196);

  float acc[16][4];
#pragma unroll
  for (int i = 0; i < 15; i++) { acc[i][0] = acc[i][1] = acc[i][2] = acc[i][3] = 0.f; }

  auto stageK = [&](int ch, int buf) {
    const unsigned sb = sbase + OFF_K + (unsigned)buf * KBUF;
    const int k0 = ch * 32;
    for (int idx = tid; idx < 120 * 4; idx += 224) {
      const int r = idx >> 2, q = (idx & 3) * 8;
      const int pix = tbl[r];
      const size_t src = ((size_t)b * 15680 + max(pix, 0)) * 256 + k0 + q;
      const int sz = (pix >= 0) ? 16 : 0;
      CP16(sb + r * 80 + q * 2, g_KLh + src, sz);
      CP16(sb + KHB + r * 80 + q * 2, g_KLl + src, sz);
    }
    CPCOMMIT();
  };
  // V staged directly from g_VL: Vt[k(32)][c(128 pad 136)] per chunk, per c-half.
  auto stageV = [&](int ch, int buf, int c0) {
    const unsigned vb = sbase + OFF_VB + (unsigned)buf * VBUF;
    const int k0 = ch * 32;
    for (int idx = tid; idx < 32 * 16; idx += 224) {
      const int rk = idx >> 4, q = (idx & 15) * 8;
      const int pix = tbl[k0 + rk];
      const size_t src = ((size_t)b * 15680 + max(pix, 0)) * 256 + c0 + q;
      const int sz = (pix >= 0) ? 16 : 0;
      CP16(vb + rk * 272 + q * 2, g_VLh + src, sz);
      CP16(vb + 8704 + rk * 272 + q * 2, g_VLl + src, sz);
    }
    CPCOMMIT();
  };

  // ---------------- S mainloop (A: reg-prefetched x; K: cp.async dbuf) ----------------
  float ar[16];
#pragma unroll
  for (int i = 0; i < 16; i++)
    ar[i] = xb[(size_t)(akb + 2 * i) * HWF];
  stageK(0, 0);

#pragma unroll 1
  for (int ch = 0; ch < 8; ch++) {
    const int buf = ch & 1;
    // split A regs to smem (previous MMAs done: loop-end sync)
#pragma unroll
    for (int i = 0; i < 16; i++) {
      unsigned short h, l; split_f32(xvalid ? ar[i] : 0.f, h, l);
      Ah[ap * 40 + akb + 2 * i] = h;
      Al[ap * 40 + akb + 2 * i] = l;
    }
    if (ch < 7) { stageK(ch + 1, buf ^ 1); CPWAIT1(); }
    else        { CPWAIT0(); }
    __syncthreads();
    if (ch < 7) {
      const int nk0 = ch * 32 + 32;
#pragma unroll
      for (int i = 0; i < 16; i++)
        ar[i] = xb[(size_t)(nk0 + akb + 2 * i) * HWF];
    }
    const unsigned bo = b_addr + (unsigned)buf * KBUF;
#pragma unroll
    for (int kk = 0; kk < 2; kk++) {
      unsigned ahf[4], alf[4];
      LDSM4(ahf, a_addr + kk * 32);
      LDSM4(alf, a_addr + 8960 + kk * 32);
#pragma unroll
      for (int nf = 0; nf + 1 < 15; nf += 2) {
        unsigned bh[4], bl4[4];
        LDSM4(bh,  bo + nf * 640 + kk * 32);
        LDSM4(bl4, bo + KHB + nf * 640 + kk * 32);
        mma_bf16(acc[nf], ahf, bh);      mma_bf16(acc[nf + 1], ahf, bh + 2);
        mma_bf16(acc[nf], alf, bh);      mma_bf16(acc[nf + 1], alf, bh + 2);
        mma_bf16(acc[nf], ahf, bl4);     mma_bf16(acc[nf + 1], ahf, bl4 + 2);
      }
      {
        unsigned bh[4], bl4[4];
        LDSM4(bh,  bo + 14 * 640 + kk * 32);
        LDSM4(bl4, bo + KHB + 14 * 640 + kk * 32);
        mma_bf16(acc[14], ahf, bh);
        mma_bf16(acc[14], alf, bh);
        mma_bf16(acc[14], ahf, bl4);
      }
    }
    __syncthreads();
  }

  // prefetch V (pass 0, chunk 0) — latency hides behind the softmax fold
  stageV(0, 0, 0);

  // ---------------- softmax fold ----------------
  float* SL = (float*)smem;              // [112][124]
  float* PL = (float*)(smem + 55552);    // [112][128]
  {
    const int row = warp * 16 + qr;
#pragma unroll
    for (int nf = 0; nf < 15; nf++) {
      const int c = nf * 8 + kc2;
      SL[row * 124 + c]           = acc[nf][0];
      SL[row * 124 + c + 1]       = acc[nf][1];
      SL[(row + 8) * 124 + c]     = acc[nf][2];
      SL[(row + 8) * 124 + c + 1] = acc[nf][3];
    }
  }
  for (int idx = tid; idx < 112 * 128; idx += 224) PL[idx] = 0.f;
  __syncthreads();
  // add the bq^T K column term t_j
  for (int idx = tid; idx < 112 * 120; idx += 224) {
    const int rr = idx / 120, j = idx - rr * 120;
    SL[rr * 124 + j] += ts[j];
  }
  __syncthreads();

  const int r = tid >> 1, hf = tid & 1;
  const int l = Lb + r;
  const int mi0 = hf * 7;
  float invs[2] = {0.f, 0.f};
  if (l < 196) {
    const float* SLr = SL + r * 124;
    float* PLr = PL + r * 128;
    {
      float mx = pass_max<9>(SLr, JR, FR, FC, CS, mi0);
      mx = fmaxf(mx, __shfl_xor_sync(0xffffffffu, mx, 1));
      float sum = pass_fold<9>(SLr, PLr, JR, FR, FC, CS, mi0, mx);
      sum += __shfl_xor_sync(0xffffffffu, sum, 1);
      invs[0] = 1.f / sum;
    }
    {
      float mx = pass_max<5>(SLr + 88, JR + 14, FR + 14, FC + 14, CS + 10, mi0);
      mx = fmaxf(mx, __shfl_xor_sync(0xffffffffu, mx, 1));
      float sum = pass_fold<5>(SLr + 88, PLr + 88, JR + 14, FR + 14, FC + 14, CS + 10, mi0, mx);
      sum += __shfl_xor_sync(0xffffffffu, sum, 1);
      invs[1] = 1.f / sum;
    }
  } else {
    __shfl_xor_sync(0xffffffffu, 0.f, 1); __shfl_xor_sync(0xffffffffu, 0.f, 1);
    __shfl_xor_sync(0xffffffffu, 0.f, 1); __shfl_xor_sync(0xffffffffu, 0.f, 1);
  }
  __syncthreads();

  // ---- write P split into smem ----
  unsigned short* Ph = (unsigned short*)(smem + OFF_PH);   // [112][136]
  unsigned short* Pl = (unsigned short*)(smem + OFF_PH + 30464);
  {
    const float* PLr = PL + r * 128;
#pragma unroll
    for (int c = 0; c < 64; c += 2) {
      const int cc = hf * 64 + c;
      const float scl = (l < 196) ? ((cc < 88) ? invs[0] : invs[1]) : 0.f;
      unsigned uh, ul;
      split2(PLr[cc] * scl, PLr[cc + 1] * scl, uh, ul);
      *(unsigned*)&Ph[r * 136 + cc] = uh;
      *(unsigned*)&Pl[r * 136 + cc] = ul;
    }
  }
  __syncthreads();

  // ---------------- AV GEMM: O[l][c] = sum_k P[l][k] V[k][c] ----------------
  const unsigned aP  = sbase + OFF_PH + ((warp * 16 + l7 + (t8 & 1) * 8) * 136 + (t8 >> 1) * 8) * 2;
  const unsigned bVt = sbase + OFF_VB + ((t8 & 1) * 8 + l7) * 272 + (t8 >> 1) * 16;
  const int php = (n >> 4) & 15, pwp = n & 15;

#pragma unroll 1
  for (int pass = 0; pass < 2; pass++) {
    const int c0 = pass * 128;
#pragma unroll
    for (int i = 0; i < 16; i++) { acc[i][0] = acc[i][1] = acc[i][2] = acc[i][3] = 0.f; }
#pragma unroll 1
    for (int ch = 0; ch < 4; ch++) {
      const int buf = ch & 1;
      if (ch + 1 < 4) { stageV(ch + 1, buf ^ 1, c0); CPWAIT1(); }
      else            { CPWAIT0(); }
      __syncthreads();
      const unsigned bo = bVt + (unsigned)buf * VBUF;
#pragma unroll
      for (int kk = 0; kk < 2; kk++) {
        unsigned ahf[4], alf[4];
        LDSM4(ahf, aP + ch * 64 + kk * 32);
        LDSM4(alf, aP + 30464 + ch * 64 + kk * 32);
        const unsigned bko = bo + (unsigned)kk * 4352;   // 16 k rows * 272 B
#pragma unroll
        for (int nf = 0; nf < 16; nf += 2) {
          unsigned bh[4], bl4[4];
          LDSM4T(bh,  bko + nf * 16);
          LDSM4T(bl4, bko + 8704 + nf * 16);
          mma_bf16(acc[nf], ahf, bh);      mma_bf16(acc[nf + 1], ahf, bh + 2);
          mma_bf16(acc[nf], alf, bh);      mma_bf16(acc[nf + 1], alf, bh + 2);
          mma_bf16(acc[nf], ahf, bl4);     mma_bf16(acc[nf + 1], ahf, bl4 + 2);
        }
      }
      __syncthreads();
    }
    if (pass == 0) stageV(0, 0, 128);   // prefetch next pass; hides behind epilogue

    float* T = (float*)smem;   // [64][133]
#pragma unroll 1
    for (int ep = 0; ep < 2; ep++) {
      __syncthreads();
      if ((warp >> 2) == ep) {
        const int lr = warp * 16 + qr - ep * 64;
#pragma unroll
        for (int nf = 0; nf < 16; nf++) {
          const int c = nf * 8 + kc2;
          T[lr * 133 + c]           = acc[nf][0];
          T[lr * 133 + c + 1]       = acc[nf][1];
          T[(lr + 8) * 133 + c]     = acc[nf][2];
          T[(lr + 8) * 133 + c + 1] = acc[nf][3];
        }
      }
      __syncthreads();
      const int nrows = ep ? 48 : 64;
      for (int idx = tid; idx < 128 * 64; idx += 224) {
        const int c = idx >> 6, lr = idx & 63;
        const int ll = Lb + ep * 64 + lr;
        if (lr < nrows && ll < 196) {
          const int hh2 = php * 14 + ll / 14, ww2 = pwp * 14 + ll % 14;
          outp[(size_t)b * IMG_B + (size_t)(c0 + c) * HWF + hh2 * 224 + ww2] = T[lr * 133 + c];
        }
      }
    }
    __syncthreads();
  }
}

// ---------------- launcher ----------------
extern "C" void kernel_launch(void* const* d_in, const int* in_sizes, int n_in,
                              void* d_out, int out_size) {
  const float* x     = (const float*)d_in[0];
  const float* skip0 = (const float*)d_in[1];
  const float* skip1 = (const float*)d_in[2];
  const float* Wq    = (const float*)d_in[3];
  const float* bq    = (const float*)d_in[4];
  const float* Wk    = (const float*)d_in[5];
  const float* bk    = (const float*)d_in[6];
  const float* Wv    = (const float*)d_in[7];
  const float* bv    = (const float*)d_in[8];
  float* out = (float*)d_out;
  (void)in_sizes; (void)n_in; (void)out_size; (void)bk;

  cudaFuncSetAttribute(proj_kernel, cudaFuncAttributeMaxDynamicSharedMemorySize, 58880);
  cudaFuncSetAttribute(attn_kernel, cudaFuncAttributeMaxDynamicSharedMemorySize, 210176);

  mqk_kernel<<<dim3(16, 16), 256>>>(Wq, Wk);       // Mqk = Wq^T Wk
  u_kernel<<<1, 256>>>(Wk, bq);                    // u = Wk^T bq
  splitW_kernel<<<128, 256>>>(Wv);                 // split {Mqk, Wv}
  t_kernel<<<245, 256>>>(skip0, skip1);            // t = u · skip
  proj_kernel<<<dim3(1120, 2), 224, 58880>>>(skip0, skip1, bv);
  attn_kernel<<<dim3(2, 1, 1024), 224, 210176>>>(x, out);
}

// round 17
// speedup vs baseline: 1.5217x; 1.5217x over previous
#include <cuda_runtime.h>
#include <cuda_bf16.h>
#include <cstdint>

#define HWF   50176
#define IMG_B 12845056
#define L2E   1.4426950408889634f

// ---------------- device scratch (split bf16 hi/lo) ----------------
__device__ unsigned short g_Xh[51380224],  g_Xl[51380224];    // x transposed: [n][l][256]
__device__ unsigned short g_KLh[16056320], g_KLl[16056320];   // Kp = (L2E·Mqk)·skip: [b][pix][256]
__device__ unsigned short g_VLh[16056320], g_VLl[16056320];   // V = Wv·skip+bv: [b][pix][256]
__device__ unsigned short g_Wh[131072], g_Wl[131072];         // split [2][256][256]: Mqk, Wv
__device__ float g_Mqk[65536];                                 // L2E · WqT·Wk fp32
__device__ float g_u[256];                                     // L2E · WkT·bq
__device__ float g_t[62720];                                   // u·skip per [b][pix]

// ---------------- helpers ----------------
__device__ __forceinline__ void split_f32(float v, unsigned short& h, unsigned short& l) {
  __nv_bfloat16 bh = __float2bfloat16(v);
  h = __bfloat16_as_ushort(bh);
  l = __bfloat16_as_ushort(__float2bfloat16(v - __bfloat162float(bh)));
}
__device__ __forceinline__ void split2(float a, float b, unsigned& uh, unsigned& ul) {
  unsigned short h0, l0, h1, l1; split_f32(a, h0, l0); split_f32(b, h1, l1);
  uh = (unsigned)h0 | ((unsigned)h1 << 16);
  ul = (unsigned)l0 | ((unsigned)l1 << 16);
}
__device__ __forceinline__ void mma_bf16(float d[4], const unsigned a[4], const unsigned b[2]) {
  asm volatile("mma.sync.aligned.m16n8k16.row.col.f32.bf16.bf16.f32 "
               "{%0,%1,%2,%3}, {%4,%5,%6,%7}, {%8,%9}, {%0,%1,%2,%3};\n"
               : "+f"(d[0]), "+f"(d[1]), "+f"(d[2]), "+f"(d[3])
               : "r"(a[0]), "r"(a[1]), "r"(a[2]), "r"(a[3]), "r"(b[0]), "r"(b[1]));
}
__device__ __forceinline__ float ex2f(float x) {
  float y;
  asm("ex2.approx.f32 %0, %1;" : "=f"(y) : "f"(x));
  return y;
}
#define LDSM4(r, addr) \
  asm volatile("ldmatrix.sync.aligned.m8n8.x4.shared.b16 {%0,%1,%2,%3},[%4];" \
               : "=r"(r[0]), "=r"(r[1]), "=r"(r[2]), "=r"(r[3]) : "r"(addr))
#define LDSM4T(r, addr) \
  asm volatile("ldmatrix.sync.aligned.m8n8.x4.trans.shared.b16 {%0,%1,%2,%3},[%4];" \
               : "=r"(r[0]), "=r"(r[1]), "=r"(r[2]), "=r"(r[3]) : "r"(addr))
#define CP16(sm, gp, sz) \
  asm volatile("cp.async.cg.shared.global [%0],[%1],16,%2;\n" :: "r"(sm), "l"(gp), "r"(sz))
#define CPCOMMIT() asm volatile("cp.async.commit_group;\n" ::: "memory")
#define CPWAIT1()  asm volatile("cp.async.wait_group 1;\n" ::: "memory")
#define CPWAIT0()  asm volatile("cp.async.wait_group 0;\n" ::: "memory")

// window pixel for patch n, window slot j (0..127). -1 = zero pad.
__device__ __forceinline__ int win_pix(int n, int j) {
  const int ah = (n >> 4) & 15, aw = n & 15;
  if (j < 81) {
    const int jr = j / 9, jc = j - jr * 9;
    const int gr = min(max(7 * ah - 1 + jr, 0), 111);
    const int gc = min(max(7 * aw - 1 + jc, 0), 111);
    return gr * 112 + gc;
  }
  if (j >= 88 && j < 113) {
    const int jj = j - 88;
    const int jr = jj / 5, jc = jj - jr * 5;
    const int gr = min(max(((7 * ah - 1) >> 1) + jr, 0), 55);
    const int gc = min(max(((7 * aw - 1) >> 1) + jc, 0), 55);
    return 12544 + gr * 56 + gc;
  }
  return -1;
}

// ---------------- Mqk = L2E · Wq^T Wk (fp32 tiled) ----------------
__global__ void __launch_bounds__(256) mqk_kernel(
    const float* __restrict__ Wq, const float* __restrict__ Wk)
{
  __shared__ float A[16][17], B[16][17];
  const int tx = threadIdx.x & 15, ty = threadIdx.x >> 4;
  const int c0 = blockIdx.x * 16, cp0 = blockIdx.y * 16;
  float acc = 0.f;
  for (int o0 = 0; o0 < 256; o0 += 16) {
    A[ty][tx] = Wq[(o0 + ty) * 256 + c0 + tx];
    B[ty][tx] = Wk[(o0 + ty) * 256 + cp0 + tx];
    __syncthreads();
#pragma unroll
    for (int o = 0; o < 16; o++) acc += A[o][ty] * B[o][tx];
    __syncthreads();
  }
  g_Mqk[(c0 + ty) * 256 + cp0 + tx] = acc * L2E;
}

// ---------------- u = L2E · Wk^T bq ----------------
__global__ void u_kernel(const float* __restrict__ Wk, const float* __restrict__ bq)
{
  const int k = threadIdx.x;
  float s = 0.f;
  for (int o = 0; o < 256; o++) s += bq[o] * Wk[o * 256 + k];
  g_u[k] = s * L2E;
}

// ---------------- t[b][pix] = u · skip ----------------
__global__ void __launch_bounds__(256) t_kernel(
    const float* __restrict__ skip0, const float* __restrict__ skip1)
{
  __shared__ float us[256];
  us[threadIdx.x] = g_u[threadIdx.x];
  __syncthreads();
  const int idx = blockIdx.x * 256 + threadIdx.x;   // < 62720 exactly (245 blocks)
  const int b = idx / 15680, pix = idx - b * 15680;
  const float* src; int hw, hwin;
  if (pix < 12544) { src = skip0; hw = pix; hwin = 12544; }
  else             { src = skip1; hw = pix - 12544; hwin = 3136; }
  const float* p = src + (size_t)b * 256 * hwin + hw;
  float s = 0.f;
  for (int k = 0; k < 256; k++) s += us[k] * p[(size_t)k * hwin];
  g_t[idx] = s;
}

// ---------------- split {Mqk, Wv} -> g_Wh/g_Wl ----------------
__global__ void __launch_bounds__(256) splitW_kernel(const float* __restrict__ Wv)
{
  const int t = blockIdx.x * 256 + threadIdx.x;   // 32768 threads x 4 elems
  const int wi = t / 16384, i = t - wi * 16384;
  const float4 v = ((const float4*)(wi == 0 ? g_Mqk : Wv))[i];
  unsigned uh0, ul0, uh1, ul1;
  split2(v.x, v.y, uh0, ul0);
  split2(v.z, v.w, uh1, ul1);
  *(uint2*)&g_Wh[t * 4] = make_uint2(uh0, uh1);
  *(uint2*)&g_Wl[t * 4] = make_uint2(ul0, ul1);
}

// ---------------- x transpose+split: [b][c][hw] -> [n][l][256] ----------------
__global__ void __launch_bounds__(256) xtrans_kernel(const float* __restrict__ x)
{
  __shared__ float sm[64][33];
  const int tx = threadIdx.x & 31, ty = threadIdx.x >> 5;
  const int p0 = blockIdx.x * 32, c0 = blockIdx.y * 64, b = blockIdx.z;
#pragma unroll
  for (int i = 0; i < 8; i++) {
    const int cl = ty + 8 * i;
    sm[cl][tx] = x[((size_t)(b * 256 + c0 + cl)) * 50176 + p0 + tx];
  }
  __syncthreads();
#pragma unroll
  for (int i = 0; i < 4; i++) {
    const int pl = ty + 8 * i;
    const int p = p0 + pl;
    const int h = p / 224, w = p - (p / 224) * 224;
    const int n = (b << 8) + (h / 14) * 16 + (w / 14);
    const int l = (h % 14) * 14 + (w % 14);
    unsigned uh, ul;
    split2(sm[2 * tx][pl], sm[2 * tx + 1][pl], uh, ul);
    const size_t dst = ((size_t)n * 196 + l) * 256 + c0 + 2 * tx;
    *(unsigned*)&g_Xh[dst] = uh;
    *(unsigned*)&g_Xl[dst] = ul;
  }
}

// ==================================================================
// Projection kernel (low-res only): Kp = Mqk'·skip ; V = Wv·skip + bv
// ==================================================================
__global__ void __launch_bounds__(224, 2) proj_kernel(
    const float* __restrict__ skip0, const float* __restrict__ skip1,
    const float* __restrict__ bv)
{
  constexpr int NF = 16;
  extern __shared__ __align__(16) unsigned char smem[];
  unsigned short* Ah = (unsigned short*)smem;            // [112][40]
  unsigned short* Al = (unsigned short*)(smem + 8960);

  const int tid = threadIdx.x, warp = tid >> 5, lane = tid & 31;
  const int qr = lane >> 2, kc2 = (lane & 3) * 2;
  const int t8 = lane >> 3, l7 = lane & 7;

  // segment decode: [0,448) Kp-s0, [448,560) Kp-s1, [560,1008) V-s0, [1008,1120) V-s1
  int t = blockIdx.x;
  const float* src;
  int hwin, offs, dst, wsel;
  if (t < 448)       {            src = skip0; hwin = 12544; offs = 0;     dst = 1; wsel = 0; }
  else if (t < 560)  { t -= 448;  src = skip1; hwin = 3136;  offs = 12544; dst = 1; wsel = 0; }
  else if (t < 1008) { t -= 560;  src = skip0; hwin = 12544; offs = 0;     dst = 2; wsel = 1; }
  else               { t -= 1008; src = skip1; hwin = 3136;  offs = 12544; dst = 2; wsel = 1; }
  const int p0 = t * 112;
  const int b = p0 / hwin;
  const int o0 = blockIdx.y * 128;
  const float* xb = src + (size_t)b * 256 * hwin + (p0 - b * hwin);
  const unsigned wbase = (unsigned)wsel * 65536 + (unsigned)o0 * 256;

  const int ap = tid % 112, akb = tid / 112;

  const unsigned sbase  = (unsigned)__cvta_generic_to_shared(smem);
  const unsigned a_addr = sbase + ((warp * 16 + l7 + (t8 & 1) * 8) * 40 + (t8 >> 1) * 8) * 2;
  const unsigned b_base = sbase + 17920 + ((l7 + (t8 >> 1) * 8) * 40 + (t8 & 1) * 8) * 2;

  float acc[NF][4];
#pragma unroll
  for (int i = 0; i < NF; i++) { acc[i][0] = acc[i][1] = acc[i][2] = acc[i][3] = 0.f; }

  auto stageB = [&](int ch, int buf) {
    const unsigned sb = sbase + 17920 + (unsigned)buf * 20480;
    const int k0 = ch * 32;
    for (int idx = tid; idx < 128 * 4; idx += 224) {
      const int r = idx >> 2, q = (idx & 3) * 8;
      const unsigned g = wbase + r * 256 + k0 + q;
      CP16(sb + r * 80 + q * 2, g_Wh + g, 16);
      CP16(sb + 10240 + r * 80 + q * 2, g_Wl + g, 16);
    }
    CPCOMMIT();
  };

  float ar[16];
#pragma unroll
  for (int i = 0; i < 16; i++)
    ar[i] = xb[(size_t)(akb + 2 * i) * hwin + ap];
  stageB(0, 0);

#pragma unroll 1
  for (int ch = 0; ch < 8; ch++) {
    const int buf = ch & 1;
#pragma unroll
    for (int i = 0; i < 16; i++) {
      unsigned short h, l; split_f32(ar[i], h, l);
      Ah[ap * 40 + akb + 2 * i] = h;
      Al[ap * 40 + akb + 2 * i] = l;
    }
    if (ch < 7) { stageB(ch + 1, buf ^ 1); CPWAIT1(); }
    else        { CPWAIT0(); }
    __syncthreads();
    if (ch < 7) {
      const int nk0 = ch * 32 + 32;
#pragma unroll
      for (int i = 0; i < 16; i++)
        ar[i] = xb[(size_t)(nk0 + akb + 2 * i) * hwin + ap];
    }
    const unsigned bo = b_base + (unsigned)buf * 20480;
#pragma unroll
    for (int kk = 0; kk < 2; kk++) {
      unsigned ahf[4], alf[4];
      LDSM4(ahf, a_addr + kk * 32);
      LDSM4(alf, a_addr + 8960 + kk * 32);
#pragma unroll
      for (int nf = 0; nf < NF; nf += 2) {
        unsigned bh[4], bl4[4];
        LDSM4(bh,  bo + nf * 640 + kk * 32);
        LDSM4(bl4, bo + 10240 + nf * 640 + kk * 32);
        mma_bf16(acc[nf], ahf, bh);      mma_bf16(acc[nf + 1], ahf, bh + 2);
        mma_bf16(acc[nf], alf, bh);      mma_bf16(acc[nf + 1], alf, bh + 2);
        mma_bf16(acc[nf], ahf, bl4);     mma_bf16(acc[nf + 1], ahf, bl4 + 2);
      }
    }
    __syncthreads();
  }

  unsigned short* dh = (dst == 2) ? g_VLh : g_KLh;
  unsigned short* dl = (dst == 2) ? g_VLl : g_KLl;
#pragma unroll
  for (int half = 0; half < 2; half++) {
    const int p = p0 + warp * 16 + qr + half * 8;
    const int pl = p - b * hwin;
    const size_t dsto = ((size_t)b * 15680 + offs + pl) * 256;
#pragma unroll
    for (int nf = 0; nf < NF; nf++) {
      const int o = o0 + nf * 8 + kc2;
      const float b0 = (dst == 2) ? bv[o] : 0.f;
      const float b1 = (dst == 2) ? bv[o + 1] : 0.f;
      unsigned uh, ul;
      split2(acc[nf][half * 2] + b0, acc[nf][half * 2 + 1] + b1, uh, ul);
      *(unsigned*)&dh[dsto + o] = uh;
      *(unsigned*)&dl[dsto + o] = ul;
    }
  }
}

// ---------------- register softmax-fold helpers ----------------
// skip0 (scale 1/2): jr(u)=(u+1)>>1 universal; fr = u even ? .75 : .25.
// Powers: weights are quarters -> G = exp2(H/4), e = G^a * G3^b.
template<int U0>
__device__ __forceinline__ float fold_s0(const float* __restrict__ SLr, float mx0, float TA[5][9])
{
  constexpr int JRA[14] = {0,1,1,2,2,3,3,4,4,5,5,6,6,7};
  float sum = 0.f;
#pragma unroll
  for (int i = 0; i < 7; i++) {
    const int u = U0 + i;
    const int jr = JRA[u];
    const float fr = (u & 1) ? 0.25f : 0.75f;
    float G[9], G3[9], Tl[9];
#pragma unroll
    for (int jc = 0; jc < 9; jc++) {
      const float a = SLr[jr * 9 + jc];
      const float h = a + fr * (SLr[jr * 9 + 9 + jc] - a) - mx0;
      G[jc] = ex2f(h * 0.25f);
      G3[jc] = G[jc] * G[jc] * G[jc];
      Tl[jc] = 0.f;
    }
#pragma unroll
    for (int v = 0; v < 14; v++) {
      const int jc = (v + 1) >> 1;
      const float fc = (v & 1) ? 0.25f : 0.75f;
      const float e = (v & 1) ? (G3[jc] * G[jc + 1]) : (G[jc] * G3[jc + 1]);
      sum += e;
      Tl[jc]     += e * (1.f - fc);
      Tl[jc + 1] += e * fc;
    }
    const int r0 = jr - (U0 ? 4 : 0);
#pragma unroll
    for (int jc = 0; jc < 9; jc++) {
      TA[r0][jc]     += (1.f - fr) * Tl[jc];
      TA[r0 + 1][jc] += fr * Tl[jc];
    }
  }
  return sum;
}

// skip1 (scale 1/4): two parity classes; fr in eighths -> G = exp2(H/8),
// e = G^(8-k) * G'[k] with k in {1,3,5,7} via power table.
template<int U0, int RP, int CP>
__device__ __forceinline__ float fold_s1(const float* __restrict__ SB, float mx1, float TB[5][5])
{
  constexpr int JP0[14] = {0,0,1,1,1,1,2,2,2,2,3,3,3,3};
  constexpr int JP1[14] = {0,0,0,0,1,1,1,1,2,2,2,2,3,3};
  constexpr float FP0[4] = {0.625f, 0.875f, 0.125f, 0.375f};
  constexpr float FP1[4] = {0.125f, 0.375f, 0.625f, 0.875f};
  float sum = 0.f;
#pragma unroll
  for (int i = 0; i < 7; i++) {
    const int u = U0 + i;
    const int jr = RP ? JP1[u] : JP0[u];
    const float fr = RP ? FP1[u & 3] : FP0[u & 3];
    float G1[5], G3[5], G5[5], G7[5], Tl[5];
#pragma unroll
    for (int jc = 0; jc < 5; jc++) {
      const float a = SB[jr * 5 + jc];
      const float h = a + fr * (SB[jr * 5 + 5 + jc] - a) - mx1;
      G1[jc] = ex2f(h * 0.125f);
      const float g2 = G1[jc] * G1[jc];
      G3[jc] = g2 * G1[jc];
      G5[jc] = G3[jc] * g2;
      G7[jc] = G5[jc] * g2;
      Tl[jc] = 0.f;
    }
#pragma unroll
    for (int v = 0; v < 14; v++) {
      const int jc = CP ? JP1[v] : JP0[v];
      const int ph = CP ? (v & 3) : ((v + 2) & 3);   // phase: fc = FP1[ph] = (2ph+1)/8
      const float fc = 0.125f + 0.25f * ph;
      float e;
      if (ph == 0)      e = G7[jc] * G1[jc + 1];   // fc = 1/8
      else if (ph == 1) e = G5[jc] * G3[jc + 1];   // fc = 3/8
      else if (ph == 2) e = G3[jc] * G5[jc + 1];   // fc = 5/8
      else              e = G1[jc] * G7[jc + 1];   // fc = 7/8
      sum += e;
      Tl[jc]     += e * (1.f - fc);
      Tl[jc + 1] += e * fc;
    }
#pragma unroll
    for (int jc = 0; jc < 5; jc++) {
      TB[jr][jc]     += (1.f - fr) * Tl[jc];
      TB[jr + 1][jc] += fr * Tl[jc];
    }
  }
  return sum;
}

// ==================================================================
// Fused attention kernel: S_low = x·Kp (+t, log2 domain) -> register
// softmax fold (no atomics) -> P smem -> AV GEMM -> unpatchified out.
// ==================================================================
__global__ void __launch_bounds__(224, 1) attn_kernel(float* __restrict__ outp)
{
  extern __shared__ __align__(16) unsigned char smem[];
  const unsigned sbase = (unsigned)__cvta_generic_to_shared(smem);
  constexpr unsigned OFF_PH = 114432, OFF_VB = 175360, VBUF = 17408;
  int*   tbl = (int*)(smem + 112896);   // 128 ints
  float* ts  = (float*)(smem + 113408); // 120 floats

  const int tid = threadIdx.x, warp = tid >> 5, lane = tid & 31;
  const int qr = lane >> 2, kc2 = (lane & 3) * 2;
  const int t8 = lane >> 3, l7 = lane & 7;
  const int n = blockIdx.z, b = n >> 8;
  const int Lb = blockIdx.x * 112;
  const int ah = (n >> 4) & 15, aw = n & 15;

  for (int j = tid; j < 128; j += 224) tbl[j] = win_pix(n, j);
  __syncthreads();
  for (int j = tid; j < 120; j += 224)
    ts[j] = (tbl[j] >= 0) ? g_t[b * 15680 + tbl[j]] : 0.f;

  const unsigned a_addr = sbase + ((warp * 16 + l7 + (t8 & 1) * 8) * 40 + (t8 >> 1) * 8) * 2;
  const unsigned b_addr = sbase + 17920 + ((l7 + (t8 >> 1) * 8) * 40 + (t8 & 1) * 8) * 2;
  constexpr int BHB = 9600, BUFSZ = 37120;

  float acc[16][4];
#pragma unroll
  for (int i = 0; i < 15; i++) { acc[i][0] = acc[i][1] = acc[i][2] = acc[i][3] = 0.f; }

  auto stage = [&](int ch, int buf) {
    const unsigned sb = sbase + (unsigned)buf * BUFSZ;
    const int k0 = ch * 32;
    for (int idx = tid; idx < 112 * 4; idx += 224) {
      const int r = idx >> 2, q = (idx & 3) * 8;
      const int l = Lb + r;
      const size_t src = ((size_t)n * 196 + min(l, 195)) * 256 + k0 + q;
      const int sz = (l < 196) ? 16 : 0;
      CP16(sb + r * 80 + q * 2, g_Xh + src, sz);
      CP16(sb + 8960 + r * 80 + q * 2, g_Xl + src, sz);
    }
    for (int idx = tid; idx < 120 * 4; idx += 224) {
      const int r = idx >> 2, q = (idx & 3) * 8;
      const int pix = tbl[r];
      const size_t src = ((size_t)b * 15680 + max(pix, 0)) * 256 + k0 + q;
      const int sz = (pix >= 0) ? 16 : 0;
      CP16(sb + 17920 + r * 80 + q * 2, g_KLh + src, sz);
      CP16(sb + 27520 + r * 80 + q * 2, g_KLl + src, sz);
    }
    CPCOMMIT();
  };
  auto stageV = [&](int ch, int buf, int c0) {
    const unsigned vb = sbase + OFF_VB + (unsigned)buf * VBUF;
    const int k0 = ch * 32;
    for (int idx = tid; idx < 32 * 16; idx += 224) {
      const int rk = idx >> 4, q = (idx & 15) * 8;
      const int pix = tbl[k0 + rk];
      const size_t src = ((size_t)b * 15680 + max(pix, 0)) * 256 + c0 + q;
      const int sz = (pix >= 0) ? 16 : 0;
      CP16(vb + rk * 272 + q * 2, g_VLh + src, sz);
      CP16(vb + 8704 + rk * 272 + q * 2, g_VLl + src, sz);
    }
    CPCOMMIT();
  };

  // ---------------- S mainloop ----------------
  stage(0, 0);
#pragma unroll 1
  for (int ch = 0; ch < 8; ch++) {
    const int buf = ch & 1;
    if (ch + 1 < 8) { stage(ch + 1, buf ^ 1); CPWAIT1(); }
    else            { CPWAIT0(); }
    __syncthreads();
    const unsigned ao = a_addr + (unsigned)buf * BUFSZ;
    const unsigned bo = b_addr + (unsigned)buf * BUFSZ;
#pragma unroll
    for (int kk = 0; kk < 2; kk++) {
      unsigned ahf[4], alf[4];
      LDSM4(ahf, ao + kk * 32);
      LDSM4(alf, ao + 8960 + kk * 32);
#pragma unroll
      for (int nf = 0; nf + 1 < 15; nf += 2) {
        unsigned bh[4], bl4[4];
        LDSM4(bh,  bo + nf * 640 + kk * 32);
        LDSM4(bl4, bo + BHB + nf * 640 + kk * 32);
        mma_bf16(acc[nf], ahf, bh);      mma_bf16(acc[nf + 1], ahf, bh + 2);
        mma_bf16(acc[nf], alf, bh);      mma_bf16(acc[nf + 1], alf, bh + 2);
        mma_bf16(acc[nf], ahf, bl4);     mma_bf16(acc[nf + 1], ahf, bl4 + 2);
      }
      {
        unsigned bh[4], bl4[4];
        LDSM4(bh,  bo + 14 * 640 + kk * 32);
        LDSM4(bl4, bo + BHB + 14 * 640 + kk * 32);
        mma_bf16(acc[14], ahf, bh);
        mma_bf16(acc[14], alf, bh);
        mma_bf16(acc[14], ahf, bl4);
      }
    }
    __syncthreads();
  }

  // prefetch V (pass 0, chunk 0) — latency hides behind the softmax fold
  stageV(0, 0, 0);

  // ---------------- softmax fold (registers, no atomics) ----------------
  float* SL = (float*)smem;              // [112][124]
  float* PL = (float*)(smem + 55552);    // [112][128]
  {
    const int row = warp * 16 + qr;
#pragma unroll
    for (int nf = 0; nf < 15; nf++) {
      const int c = nf * 8 + kc2;
      SL[row * 124 + c]           = acc[nf][0];
      SL[row * 124 + c + 1]       = acc[nf][1];
      SL[(row + 8) * 124 + c]     = acc[nf][2];
      SL[(row + 8) * 124 + c + 1] = acc[nf][3];
    }
  }
  __syncthreads();
  for (int idx = tid; idx < 112 * 120; idx += 224) {
    const int rr = idx / 120, j = idx - rr * 120;
    SL[rr * 124 + j] += ts[j];
  }
  __syncthreads();

  const int r = tid >> 1, hf = tid & 1;
  const int l = Lb + r;
  const float* SLr = SL + r * 124;
  float* PLr = PL + r * 128;

  // corner maxes (upper bound of interpolated max — exact softmax invariance)
  float mx0 = -1e30f, mx1 = -1e30f;
  for (int j = hf; j < 81; j += 2) mx0 = fmaxf(mx0, SLr[j]);
  mx0 = fmaxf(mx0, __shfl_xor_sync(0xffffffffu, mx0, 1));
#pragma unroll
  for (int j = 88 + hf; j < 113; j += 2) mx1 = fmaxf(mx1, SLr[j]);
  mx1 = fmaxf(mx1, __shfl_xor_sync(0xffffffffu, mx1, 1));

  float sum0, sum1;
  { // ---- skip 0 ----
    float TA[5][9];
#pragma unroll
    for (int i = 0; i < 5; i++)
#pragma unroll
      for (int jc = 0; jc < 9; jc++) TA[i][jc] = 0.f;
    sum0 = hf ? fold_s0<7>(SLr, mx0, TA) : fold_s0<0>(SLr, mx0, TA);
    sum0 += __shfl_xor_sync(0xffffffffu, sum0, 1);
#pragma unroll
    for (int jc = 0; jc < 9; jc++) {
      const float mine = hf ? TA[0][jc] : TA[4][jc];
      const float oth = __shfl_xor_sync(0xffffffffu, mine, 1);
      if (hf == 0) {
#pragma unroll
        for (int i = 0; i < 4; i++) PLr[i * 9 + jc] = TA[i][jc];
        PLr[36 + jc] = TA[4][jc] + oth;
      } else {
#pragma unroll
        for (int i = 1; i < 5; i++) PLr[(i + 4) * 9 + jc] = TA[i][jc];
      }
    }
  }
  { // ---- skip 1 ----
    float TB[5][5];
#pragma unroll
    for (int i = 0; i < 5; i++)
#pragma unroll
      for (int jc = 0; jc < 5; jc++) TB[i][jc] = 0.f;
    const int rp = ah & 1, cp = aw & 1;
    const float* SB = SLr + 88;
    if (hf == 0) {
      if (rp == 0) sum1 = cp ? fold_s1<0,0,1>(SB, mx1, TB) : fold_s1<0,0,0>(SB, mx1, TB);
      else         sum1 = cp ? fold_s1<0,1,1>(SB, mx1, TB) : fold_s1<0,1,0>(SB, mx1, TB);
    } else {
      if (rp == 0) sum1 = cp ? fold_s1<7,0,1>(SB, mx1, TB) : fold_s1<7,0,0>(SB, mx1, TB);
      else         sum1 = cp ? fold_s1<7,1,1>(SB, mx1, TB) : fold_s1<7,1,0>(SB, mx1, TB);
    }
    sum1 += __shfl_xor_sync(0xffffffffu, sum1, 1);
#pragma unroll
    for (int i = 0; i < 5; i++)
#pragma unroll
      for (int jc = 0; jc < 5; jc++) {
        const float tot = TB[i][jc] + __shfl_xor_sync(0xffffffffu, TB[i][jc], 1);
        if ((hf == 0) ? (i < 3) : (i >= 3)) PLr[88 + i * 5 + jc] = tot;
      }
  }
  const float invs0 = 1.f / sum0, invs1 = 1.f / sum1;
  __syncthreads();

  // ---- write P split into smem (dead slots + invalid rows forced to 0) ----
  unsigned short* Ph = (unsigned short*)(smem + OFF_PH);   // [112][136]
  unsigned short* Pl = (unsigned short*)(smem + OFF_PH + 30464);
  {
    const bool okrow = (l < 196);
#pragma unroll
    for (int c = 0; c < 64; c += 2) {
      const int cc = hf * 64 + c;
      const float scl = (cc < 88) ? invs0 : invs1;
      const bool ok0 = okrow && (cc < 81 || (cc >= 88 && cc < 113));
      const bool ok1 = okrow && (cc + 1 < 81 || (cc + 1 >= 88 && cc + 1 < 113));
      const float p0 = ok0 ? PLr[cc] * scl : 0.f;
      const float p1 = ok1 ? PLr[cc + 1] * scl : 0.f;
      unsigned uh, ul;
      split2(p0, p1, uh, ul);
      *(unsigned*)&Ph[r * 136 + cc] = uh;
      *(unsigned*)&Pl[r * 136 + cc] = ul;
    }
  }
  __syncthreads();

  // ---------------- AV GEMM: O[l][c] = sum_k P[l][k] V[k][c] ----------------
  const unsigned aP  = sbase + OFF_PH + ((warp * 16 + l7 + (t8 & 1) * 8) * 136 + (t8 >> 1) * 8) * 2;
  const unsigned bVt = sbase + OFF_VB + ((t8 & 1) * 8 + l7) * 272 + (t8 >> 1) * 16;
  const int php = (n >> 4) & 15, pwp = n & 15;

#pragma unroll 1
  for (int pass = 0; pass < 2; pass++) {
    const int c0 = pass * 128;
#pragma unroll
    for (int i = 0; i < 16; i++) { acc[i][0] = acc[i][1] = acc[i][2] = acc[i][3] = 0.f; }
#pragma unroll 1
    for (int ch = 0; ch < 4; ch++) {
      const int buf = ch & 1;
      if (ch + 1 < 4) { stageV(ch + 1, buf ^ 1, c0); CPWAIT1(); }
      else            { CPWAIT0(); }
      __syncthreads();
      const unsigned bo = bVt + (unsigned)buf * VBUF;
#pragma unroll
      for (int kk = 0; kk < 2; kk++) {
        unsigned ahf[4], alf[4];
        LDSM4(ahf, aP + ch * 64 + kk * 32);
        LDSM4(alf, aP + 30464 + ch * 64 + kk * 32);
        const unsigned bko = bo + (unsigned)kk * 4352;   // 16 k rows * 272 B
#pragma unroll
        for (int nf = 0; nf < 16; nf += 2) {
          unsigned bh[4], bl4[4];
          LDSM4T(bh,  bko + nf * 16);
          LDSM4T(bl4, bko + 8704 + nf * 16);
          mma_bf16(acc[nf], ahf, bh);      mma_bf16(acc[nf + 1], ahf, bh + 2);
          mma_bf16(acc[nf], alf, bh);      mma_bf16(acc[nf + 1], alf, bh + 2);
          mma_bf16(acc[nf], ahf, bl4);     mma_bf16(acc[nf + 1], ahf, bl4 + 2);
        }
      }
      __syncthreads();
    }
    if (pass == 0) stageV(0, 0, 128);   // prefetch next pass; hides behind epilogue

    float* T = (float*)smem;   // [64][133]
#pragma unroll 1
    for (int ep = 0; ep < 2; ep++) {
      __syncthreads();
      if ((warp >> 2) == ep) {
        const int lr = warp * 16 + qr - ep * 64;
#pragma unroll
        for (int nf = 0; nf < 16; nf++) {
          const int c = nf * 8 + kc2;
          T[lr * 133 + c]           = acc[nf][0];
          T[lr * 133 + c + 1]       = acc[nf][1];
          T[(lr + 8) * 133 + c]     = acc[nf][2];
          T[(lr + 8) * 133 + c + 1] = acc[nf][3];
        }
      }
      __syncthreads();
      const int nrows = ep ? 48 : 64;
      for (int idx = tid; idx < 128 * 64; idx += 224) {
        const int c = idx >> 6, lr = idx & 63;
        const int ll = Lb + ep * 64 + lr;
        if (lr < nrows && ll < 196) {
          const int hh2 = php * 14 + ll / 14, ww2 = pwp * 14 + ll % 14;
          outp[(size_t)b * IMG_B + (size_t)(c0 + c) * HWF + hh2 * 224 + ww2] = T[lr * 133 + c];
        }
      }
    }
    __syncthreads();
  }
}

// ---------------- launcher ----------------
extern "C" void kernel_launch(void* const* d_in, const int* in_sizes, int n_in,
                              void* d_out, int out_size) {
  const float* x     = (const float*)d_in[0];
  const float* skip0 = (const float*)d_in[1];
  const float* skip1 = (const float*)d_in[2];
  const float* Wq    = (const float*)d_in[3];
  const float* bq    = (const float*)d_in[4];
  const float* Wk    = (const float*)d_in[5];
  const float* bk    = (const float*)d_in[6];
  const float* Wv    = (const float*)d_in[7];
  const float* bv    = (const float*)d_in[8];
  float* out = (float*)d_out;
  (void)in_sizes; (void)n_in; (void)out_size; (void)bk;

  cudaFuncSetAttribute(proj_kernel, cudaFuncAttributeMaxDynamicSharedMemorySize, 58880);
  cudaFuncSetAttribute(attn_kernel, cudaFuncAttributeMaxDynamicSharedMemorySize, 210176);

  mqk_kernel<<<dim3(16, 16), 256>>>(Wq, Wk);       // Mqk = L2E·Wq^T Wk
  u_kernel<<<1, 256>>>(Wk, bq);                    // u = L2E·Wk^T bq
  splitW_kernel<<<128, 256>>>(Wv);                 // split {Mqk, Wv}
  t_kernel<<<245, 256>>>(skip0, skip1);            // t = u · skip
  xtrans_kernel<<<dim3(1568, 4, 4), 256>>>(x);     // x -> [n][l][256] split
  proj_kernel<<<dim3(1120, 2), 224, 58880>>>(skip0, skip1, bv);
  attn_kernel<<<dim3(2, 1, 1024), 224, 210176>>>(out);
}